// round 8
// baseline (speedup 1.0000x reference)
#include <cuda_runtime.h>
#include <cuda_fp16.h>
#include <math.h>

#define NN 100000
#define EE 1600000
#define FF 16
#define HH 128
#define NB 196            // scan blocks: ceil(NN/512)

// ---------------- scratch (device globals; no allocation allowed) ----------
__device__ __align__(16) __half2 g_Ah[(size_t)NN * 64];  // h @ W_h (fp16, 256B/row)
__device__ __align__(16) float g_B[(size_t)NN * HH];     // feat @ W_f + b_nm
__device__ __align__(16) __half g_W1h[HH * HH];          // W_out1 in fp16
__device__ float g_as[NN];
__device__ float g_ad[NN];
__device__ int   g_deg[NN];
__device__ int   g_off[NN + 1];
__device__ int   g_cur[NN];
__device__ int   g_bsum[NB];
__device__ int   g_bbase[NB];
__device__ __align__(16) int4 g_elb[EE];        // CSR-ordered (src, ee, ee*bit, 0)
__device__ __align__(16) float g_W2h[64 * HH];
__device__ __align__(16) float g_bA[HH];
__device__ float g_c;

__device__ __forceinline__ float lrelu(float x, float s) { return fmaxf(x, s * x); }

// packed fp32x2 helpers (Blackwell FFMA2: 2x fp32 FMA issue rate)
__device__ __forceinline__ unsigned long long pk2(float x, float y) {
    unsigned long long r; asm("mov.b64 %0,{%1,%2};" : "=l"(r) : "f"(x), "f"(y)); return r;
}
__device__ __forceinline__ float2 upk2(unsigned long long v) {
    float2 r; asm("mov.b64 {%0,%1},%2;" : "=f"(r.x), "=f"(r.y) : "l"(v)); return r;
}
__device__ __forceinline__ unsigned long long fma2(unsigned long long a,
                                                   unsigned long long b,
                                                   unsigned long long c) {
    unsigned long long d;
    asm("fma.rn.f32x2 %0,%1,%2,%3;" : "=l"(d) : "l"(a), "l"(b), "l"(c));
    return d;
}

// ---------------- k0: fold W_self2 into W_h; bias; scalar c ----------------
__global__ void k0_prep(const float* __restrict__ W_self2,
                        const float* __restrict__ b_self2,
                        const float* __restrict__ W_nm,
                        const float* __restrict__ attn) {
    int j = threadIdx.x;          // 0..127
    int i = blockIdx.x;           // 0..64
    if (i < 64) {
        float acc = 0.f;
        for (int k = 0; k < 128; ++k)
            acc = fmaf(W_self2[i * 128 + k], W_nm[k * 128 + j], acc);
        g_W2h[i * 128 + j] = acc;
    } else {
        float acc = 0.f;
        for (int k = 0; k < 128; ++k)
            acc = fmaf(b_self2[k], W_nm[k * 128 + j], acc);
        g_bA[j] = acc;
        __shared__ float red[128];
        red[j] = W_nm[128 * 128 + j] * attn[j];   // row 128 of W_nm = w_b
        __syncthreads();
        for (int s = 64; s > 0; s >>= 1) {
            if (j < s) red[j] += red[j + s];
            __syncthreads();
        }
        if (j == 0) g_c = red[0];
    }
}

// ---------------- k0b: W_out1 -> fp16 ---------------------------------------
__global__ void k0b_w1h(const float* __restrict__ W1) {
    int i = blockIdx.x * blockDim.x + threadIdx.x;
    if (i < HH * HH) g_W1h[i] = __float2half_rn(W1[i]);
}

// ---------------- k1: per-node A(fp16), B, a_s, a_d -------------------------
// 4 nodes per warp per iteration: each SMEM weight load amortized over 4 nodes
#define NPW 4
__global__ __launch_bounds__(256) void k1_node(
    const float* __restrict__ feat,
    const float* __restrict__ W1, const float* __restrict__ b1,
    const float* __restrict__ W_nm, const float* __restrict__ b_nm,
    const float* __restrict__ attn) {
    __shared__ __align__(16) float sW1[16 * 64];
    __shared__ __align__(16) float sW2h[64 * 128];
    __shared__ __align__(16) float sWf[16 * 128];
    __shared__ __align__(16) float sb1[64];
    __shared__ __align__(16) float sbnm[128];
    __shared__ __align__(16) float sbA[128];
    __shared__ __align__(16) float sattn[128];
    int tid = threadIdx.x;
    for (int i = tid; i < 16 * 64; i += 256) sW1[i] = W1[i];
    for (int i = tid; i < 64 * 128; i += 256) sW2h[i] = g_W2h[i];
    for (int i = tid; i < 16 * 128; i += 256) sWf[i] = W_nm[129 * 128 + i];
    if (tid < 64) sb1[tid] = b1[tid];
    if (tid < 128) { sbnm[tid] = b_nm[tid]; sbA[tid] = g_bA[tid]; sattn[tid] = attn[tid]; }
    __syncthreads();

    int warp = tid >> 5, lane = tid & 31;
    const unsigned FULL = 0xffffffffu;
    int l4 = 4 * lane;
    const int STRIDE = 8 * NPW;   // nodes per block per iteration

    for (int base = blockIdx.x * STRIDE; base < NN; base += gridDim.x * STRIDE) {
        int v0 = base + warp * NPW;
        if (v0 >= NN) continue;
        bool full = (v0 + NPW <= NN);

        float f[NPW];
#pragma unroll
        for (int i = 0; i < NPW; ++i) {
            int v = v0 + i;
            f[i] = (lane < 16 && (full || v < NN)) ? feat[(size_t)v * 16 + lane] : 0.f;
        }

        float u0[NPW], u1[NPW];
#pragma unroll
        for (int i = 0; i < NPW; ++i) { u0[i] = sb1[lane]; u1[i] = sb1[lane + 32]; }
#pragma unroll
        for (int k = 0; k < 16; ++k) {
            float w0 = sW1[k * 64 + lane];
            float w1 = sW1[k * 64 + lane + 32];
#pragma unroll
            for (int i = 0; i < NPW; ++i) {
                float fk = __shfl_sync(FULL, f[i], k);
                u0[i] = fmaf(fk, w0, u0[i]);
                u1[i] = fmaf(fk, w1, u1[i]);
            }
        }
#pragma unroll
        for (int i = 0; i < NPW; ++i) {
            u0[i] = lrelu(u0[i], 0.1f);
            u1[i] = lrelu(u1[i], 0.1f);
        }

        unsigned long long a0[NPW], a1[NPW];
#pragma unroll
        for (int i = 0; i < NPW; ++i) {
            a0[i] = pk2(sbA[l4], sbA[l4 + 1]);
            a1[i] = pk2(sbA[l4 + 2], sbA[l4 + 3]);
        }
#pragma unroll 8
        for (int k = 0; k < 64; ++k) {
            ulonglong2 w = *(const ulonglong2*)&sW2h[k * 128 + l4];
#pragma unroll
            for (int i = 0; i < NPW; ++i) {
                float uk = (k < 32) ? __shfl_sync(FULL, u0[i], k)
                                    : __shfl_sync(FULL, u1[i], k - 32);
                unsigned long long uu = pk2(uk, uk);
                a0[i] = fma2(uu, w.x, a0[i]);
                a1[i] = fma2(uu, w.y, a1[i]);
            }
        }
        float4 at = *(const float4*)&sattn[l4];
        float av4[NPW];
#pragma unroll
        for (int i = 0; i < NPW; ++i) {
            int v = v0 + i;
            if (!full && v >= NN) { av4[i] = 0.f; continue; }
            float2 x01 = upk2(a0[i]), x23 = upk2(a1[i]);
            __half2 h0 = __floats2half2_rn(x01.x, x01.y);
            __half2 h1 = __floats2half2_rn(x23.x, x23.y);
            uint2 hp;
            hp.x = *(unsigned*)&h0;
            hp.y = *(unsigned*)&h1;
            *(uint2*)&g_Ah[(size_t)v * 64 + 2 * lane] = hp;
            av4[i] = x01.x * at.x + x01.y * at.y + x23.x * at.z + x23.y * at.w;
        }

        unsigned long long c0[NPW], c1[NPW];
#pragma unroll
        for (int i = 0; i < NPW; ++i) {
            c0[i] = pk2(sbnm[l4], sbnm[l4 + 1]);
            c1[i] = pk2(sbnm[l4 + 2], sbnm[l4 + 3]);
        }
#pragma unroll
        for (int k = 0; k < 16; ++k) {
            ulonglong2 w = *(const ulonglong2*)&sWf[k * 128 + l4];
#pragma unroll
            for (int i = 0; i < NPW; ++i) {
                float fk = __shfl_sync(FULL, f[i], k);
                unsigned long long ff = pk2(fk, fk);
                c0[i] = fma2(ff, w.x, c0[i]);
                c1[i] = fma2(ff, w.y, c1[i]);
            }
        }
#pragma unroll
        for (int i = 0; i < NPW; ++i) {
            int v = v0 + i;
            if (!full && v >= NN) continue;
            float2 b01 = upk2(c0[i]), b23 = upk2(c1[i]);
            float4 b = make_float4(b01.x, b01.y, b23.x, b23.y);
            *(float4*)&g_B[(size_t)v * 128 + l4] = b;
            float ps = av4[i];
            float pd = b.x * at.x + b.y * at.y + b.z * at.z + b.w * at.w;
#pragma unroll
            for (int s = 16; s > 0; s >>= 1) {
                ps += __shfl_xor_sync(FULL, ps, s);
                pd += __shfl_xor_sync(FULL, pd, s);
            }
            if (lane == 0) { g_as[v] = ps; g_ad[v] = pd; }
        }
    }
}

// ---------------- CSR build -------------------------------------------------
__global__ void k2_zero() {
    int i = blockIdx.x * blockDim.x + threadIdx.x;
    if (i < NN) g_deg[i] = 0;
}
__global__ void k2_hist(const int* __restrict__ dst) {
    int i = blockIdx.x * blockDim.x + threadIdx.x;
    if (i < EE) atomicAdd(&g_deg[dst[i]], 1);
}

// 3-phase parallel exclusive scan of g_deg -> g_off / g_cur
__global__ __launch_bounds__(512) void kS1_sum() {
    __shared__ int s[512];
    int tid = threadIdx.x;
    int i = blockIdx.x * 512 + tid;
    int v = (i < NN) ? g_deg[i] : 0;
    s[tid] = v;
    __syncthreads();
#pragma unroll
    for (int o = 256; o > 0; o >>= 1) {
        if (tid < o) s[tid] += s[tid + o];
        __syncthreads();
    }
    if (tid == 0) g_bsum[blockIdx.x] = s[0];
}
__global__ __launch_bounds__(256) void kS2_scanb() {
    __shared__ int s[256];
    int tid = threadIdx.x;
    int v = (tid < NB) ? g_bsum[tid] : 0;
    s[tid] = v;
    __syncthreads();
    for (int o = 1; o < 256; o <<= 1) {
        int t = (tid >= o) ? s[tid - o] : 0;
        __syncthreads();
        s[tid] += t;
        __syncthreads();
    }
    if (tid < NB) g_bbase[tid] = s[tid] - v;   // exclusive
    if (tid == NB - 1) g_off[NN] = s[tid];     // total
}
__global__ __launch_bounds__(512) void kS3_local() {
    __shared__ int s[512];
    int tid = threadIdx.x;
    int i = blockIdx.x * 512 + tid;
    int v = (i < NN) ? g_deg[i] : 0;
    s[tid] = v;
    __syncthreads();
    for (int o = 1; o < 512; o <<= 1) {
        int t = (tid >= o) ? s[tid - o] : 0;
        __syncthreads();
        s[tid] += t;
        __syncthreads();
    }
    if (i < NN) {
        int excl = s[tid] - v + g_bbase[blockIdx.x];
        g_off[i] = excl;
        g_cur[i] = excl;
    }
}

// scatter + edge logit + exp folded in; single 16B record per edge
__global__ void k2_scatter(const int* __restrict__ src,
                           const int* __restrict__ dst,
                           const float* __restrict__ bit) {
    int i = blockIdx.x * blockDim.x + threadIdx.x;
    if (i < EE) {
        int s = src[i], d = dst[i];
        float bv = bit[i];
        float lg = g_as[s] + g_ad[d] + g_c * bv;
        lg = fmaxf(lg, 0.2f * lg);
        float ee = __expf(lg);
        int pos = atomicAdd(&g_cur[d], 1);
        g_elb[pos] = make_int4(s, __float_as_int(ee), __float_as_int(ee * bv), 0);
    }
}

// ---------------- k3: softmax-agg + out MLP fused (warp per node) ----------
__global__ __launch_bounds__(256) void k3_fused(
    const float* __restrict__ W_nm,
    const float* __restrict__ b1,
    const float* __restrict__ W2, const float* __restrict__ b2,
    float* __restrict__ out) {
    __shared__ __align__(16) float sb1[128];
    __shared__ __align__(16) float sW2[128];
    __shared__ __align__(16) float swb[128];
    int tid = threadIdx.x;
    if (tid < 128) { sb1[tid] = b1[tid]; sW2[tid] = W2[tid]; swb[tid] = W_nm[128 * 128 + tid]; }
    __syncthreads();
    float b2v = b2[0];

    int warp = tid >> 5, lane = tid & 31;
    int l4 = 4 * lane;
    const unsigned FULL = 0xffffffffu;

    int v = blockIdx.x * 8 + warp;
    if (v >= NN) return;

    int s0 = g_off[v], s1 = g_off[v + 1];
    float4 hn = make_float4(0.f, 0.f, 0.f, 0.f);
    if (s0 < s1) {
        unsigned long long acc0 = 0ull, acc1 = 0ull;
        float se = 0.f, st = 0.f;
        for (int cb = s0; cb < s1; cb += 32) {
            int n = min(32, s1 - cb);
            int4 md = make_int4(0, 0, 0, 0);
            if (lane < n) md = __ldg(&g_elb[cb + lane]);
            int   svl = md.x;
            float eel = __int_as_float(md.y);
            se += eel;                       // 0 for inactive lanes
            st += __int_as_float(md.z);

            // software-pipelined gather: 8 A-rows in flight
            for (int jb = 0; jb < n; jb += 8) {
                int m = min(8, n - jb);
                uint2 raw[8]; float eev[8];
#pragma unroll
                for (int t = 0; t < 8; ++t) {
                    if (t < m) {
                        int sv = __shfl_sync(FULL, svl, jb + t);
                        eev[t] = __shfl_sync(FULL, eel, jb + t);
                        raw[t] = __ldg((const uint2*)&g_Ah[(size_t)sv * 64 + 2 * lane]);
                    }
                }
#pragma unroll
                for (int t = 0; t < 8; ++t) {
                    if (t < m) {
                        float2 f0 = __half22float2(*(__half2*)&raw[t].x);
                        float2 f1 = __half22float2(*(__half2*)&raw[t].y);
                        unsigned long long ev = pk2(eev[t], eev[t]);
                        acc0 = fma2(ev, pk2(f0.x, f0.y), acc0);
                        acc1 = fma2(ev, pk2(f1.x, f1.y), acc1);
                    }
                }
            }
        }
#pragma unroll
        for (int o = 16; o > 0; o >>= 1) {
            se += __shfl_xor_sync(FULL, se, o);
            st += __shfl_xor_sync(FULL, st, o);
        }
        float inv = 1.f / se;
        float tb = st * inv;
        float2 a01 = upk2(acc0), a23 = upk2(acc1);
        float4 B4 = __ldg((const float4*)&g_B[(size_t)v * 128 + l4]);
        float4 wb = *(const float4*)&swb[l4];
        hn.x = fmaxf(fmaf(a01.x, inv, B4.x) + wb.x * tb, 0.f);
        hn.y = fmaxf(fmaf(a01.y, inv, B4.y) + wb.y * tb, 0.f);
        hn.z = fmaxf(fmaf(a23.x, inv, B4.z) + wb.z * tb, 0.f);
        hn.w = fmaxf(fmaf(a23.y, inv, B4.w) + wb.w * tb, 0.f);
    }

    // out MLP: acc = lrelu(hn @ W_out1 + b_out1); out = acc . W_out2 + b2
    // W_out1 in fp16 (halves L1 wavefronts: 256B/row-segment instead of 512B)
    unsigned long long o0 = pk2(sb1[l4], sb1[l4 + 1]);
    unsigned long long o1 = pk2(sb1[l4 + 2], sb1[l4 + 3]);
#pragma unroll 8
    for (int k = 0; k < 128; ++k) {
        float s;
        switch (k & 3) {
            case 0: s = hn.x; break;
            case 1: s = hn.y; break;
            case 2: s = hn.z; break;
            default: s = hn.w; break;
        }
        float val = __shfl_sync(FULL, s, k >> 2);
        if (val != 0.f) {          // hn is post-ReLU: ~half zeros, warp-uniform skip
            uint2 w = __ldg((const uint2*)&g_W1h[k * 128 + l4]);
            float2 w01 = __half22float2(*(__half2*)&w.x);
            float2 w23 = __half22float2(*(__half2*)&w.y);
            unsigned long long vv = pk2(val, val);
            o0 = fma2(vv, pk2(w01.x, w01.y), o0);
            o1 = fma2(vv, pk2(w23.x, w23.y), o1);
        }
    }
    float2 q01 = upk2(o0), q23 = upk2(o1);
    float4 acc = make_float4(lrelu(q01.x, 0.1f), lrelu(q01.y, 0.1f),
                             lrelu(q23.x, 0.1f), lrelu(q23.y, 0.1f));
    float4 w2 = *(const float4*)&sW2[l4];
    float p = acc.x * w2.x + acc.y * w2.y + acc.z * w2.z + acc.w * w2.w;
#pragma unroll
    for (int o = 16; o > 0; o >>= 1) p += __shfl_xor_sync(FULL, p, o);
    if (lane == 0) out[v] = p + b2v;
}

// ---------------- launch -----------------------------------------------------
extern "C" void kernel_launch(void* const* d_in, const int* in_sizes, int n_in,
                              void* d_out, int out_size) {
    const float* feat    = (const float*)d_in[0];
    const float* bit     = (const float*)d_in[1];
    const int*   src     = (const int*)d_in[2];
    const int*   dst     = (const int*)d_in[3];
    const float* W_self1 = (const float*)d_in[4];
    const float* b_self1 = (const float*)d_in[5];
    const float* W_self2 = (const float*)d_in[6];
    const float* b_self2 = (const float*)d_in[7];
    const float* W_nm    = (const float*)d_in[8];
    const float* b_nm    = (const float*)d_in[9];
    const float* attn    = (const float*)d_in[10];
    const float* W_out1  = (const float*)d_in[11];
    const float* b_out1  = (const float*)d_in[12];
    const float* W_out2  = (const float*)d_in[13];
    const float* b_out2  = (const float*)d_in[14];
    float* out = (float*)d_out;

    k2_zero<<<(NN + 255) / 256, 256>>>();
    k0_prep<<<65, 128>>>(W_self2, b_self2, W_nm, attn);
    k2_hist<<<(EE + 255) / 256, 256>>>(dst);
    k1_node<<<592, 256>>>(feat, W_self1, b_self1, W_nm, b_nm, attn);
    k0b_w1h<<<(HH * HH + 255) / 256, 256>>>(W_out1);
    kS1_sum<<<NB, 512>>>();
    kS2_scanb<<<1, 256>>>();
    kS3_local<<<NB, 512>>>();
    k2_scatter<<<(EE + 255) / 256, 256>>>(src, dst, bit);
    k3_fused<<<(NN + 7) / 8, 256>>>(W_nm, b_out1, W_out2, b_out2, out);
}

// round 9
// speedup vs baseline: 1.0244x; 1.0244x over previous
#include <cuda_runtime.h>
#include <cuda_fp16.h>
#include <math.h>

#define NN 100000
#define EE 1600000
#define FF 16
#define HH 128
#define NB 196            // scan blocks: ceil(NN/512)

// ---------------- scratch (device globals; no allocation allowed) ----------
__device__ __align__(16) __half2 g_Ah[(size_t)NN * 64];  // h @ W_h (fp16, 256B/row)
__device__ __align__(16) float g_B[(size_t)NN * HH];     // feat @ W_f + b_nm
__device__ float g_as[NN];
__device__ float g_ad[NN];
__device__ int   g_deg[NN];
__device__ int   g_off[NN + 1];
__device__ int   g_cur[NN];
__device__ int   g_bsum[NB];
__device__ int   g_bbase[NB];
__device__ int   g_srcv[EE];                    // CSR-ordered src node
__device__ __align__(8) float2 g_lb[EE];        // CSR-ordered (ee, ee*bit)
__device__ __align__(16) float g_W2h[64 * HH];
__device__ __align__(16) float g_bA[HH];
__device__ float g_c;

__device__ __forceinline__ float lrelu(float x, float s) { return fmaxf(x, s * x); }

// packed fp32x2 helpers (Blackwell FFMA2: 2x fp32 FMA issue rate)
__device__ __forceinline__ unsigned long long pk2(float x, float y) {
    unsigned long long r; asm("mov.b64 %0,{%1,%2};" : "=l"(r) : "f"(x), "f"(y)); return r;
}
__device__ __forceinline__ float2 upk2(unsigned long long v) {
    float2 r; asm("mov.b64 {%0,%1},%2;" : "=f"(r.x), "=f"(r.y) : "l"(v)); return r;
}
__device__ __forceinline__ unsigned long long fma2(unsigned long long a,
                                                   unsigned long long b,
                                                   unsigned long long c) {
    unsigned long long d;
    asm("fma.rn.f32x2 %0,%1,%2,%3;" : "=l"(d) : "l"(a), "l"(b), "l"(c));
    return d;
}

// ---------------- k0: fold W_self2 into W_h; bias; scalar c ----------------
__global__ void k0_prep(const float* __restrict__ W_self2,
                        const float* __restrict__ b_self2,
                        const float* __restrict__ W_nm,
                        const float* __restrict__ attn) {
    int j = threadIdx.x;          // 0..127
    int i = blockIdx.x;           // 0..64
    if (i < 64) {
        float acc = 0.f;
        for (int k = 0; k < 128; ++k)
            acc = fmaf(W_self2[i * 128 + k], W_nm[k * 128 + j], acc);
        g_W2h[i * 128 + j] = acc;
    } else {
        float acc = 0.f;
        for (int k = 0; k < 128; ++k)
            acc = fmaf(b_self2[k], W_nm[k * 128 + j], acc);
        g_bA[j] = acc;
        __shared__ float red[128];
        red[j] = W_nm[128 * 128 + j] * attn[j];   // row 128 of W_nm = w_b
        __syncthreads();
        for (int s = 64; s > 0; s >>= 1) {
            if (j < s) red[j] += red[j + s];
            __syncthreads();
        }
        if (j == 0) g_c = red[0];
    }
}

// ---------------- k1: per-node A(fp16), B, a_s, a_d -------------------------
// 8 nodes per warp per iteration: each SMEM weight load amortized over 8 nodes
// (R7/R8 profile: k1 still L1=73% crossbar-bound at NPW=4)
#define NPW 8
__global__ __launch_bounds__(256) void k1_node(
    const float* __restrict__ feat,
    const float* __restrict__ W1, const float* __restrict__ b1,
    const float* __restrict__ W_nm, const float* __restrict__ b_nm,
    const float* __restrict__ attn) {
    __shared__ __align__(16) float sW1[16 * 64];
    __shared__ __align__(16) float sW2h[64 * 128];
    __shared__ __align__(16) float sWf[16 * 128];
    __shared__ __align__(16) float sb1[64];
    __shared__ __align__(16) float sbnm[128];
    __shared__ __align__(16) float sbA[128];
    __shared__ __align__(16) float sattn[128];
    int tid = threadIdx.x;
    for (int i = tid; i < 16 * 64; i += 256) sW1[i] = W1[i];
    for (int i = tid; i < 64 * 128; i += 256) sW2h[i] = g_W2h[i];
    for (int i = tid; i < 16 * 128; i += 256) sWf[i] = W_nm[129 * 128 + i];
    if (tid < 64) sb1[tid] = b1[tid];
    if (tid < 128) { sbnm[tid] = b_nm[tid]; sbA[tid] = g_bA[tid]; sattn[tid] = attn[tid]; }
    __syncthreads();

    int warp = tid >> 5, lane = tid & 31;
    const unsigned FULL = 0xffffffffu;
    int l4 = 4 * lane;
    const int STRIDE = 8 * NPW;   // nodes per block per iteration

    for (int base = blockIdx.x * STRIDE; base < NN; base += gridDim.x * STRIDE) {
        int v0 = base + warp * NPW;
        if (v0 >= NN) continue;
        bool full = (v0 + NPW <= NN);

        float f[NPW];
#pragma unroll
        for (int i = 0; i < NPW; ++i) {
            int v = v0 + i;
            f[i] = (lane < 16 && (full || v < NN)) ? feat[(size_t)v * 16 + lane] : 0.f;
        }

        float u0[NPW], u1[NPW];
#pragma unroll
        for (int i = 0; i < NPW; ++i) { u0[i] = sb1[lane]; u1[i] = sb1[lane + 32]; }
#pragma unroll
        for (int k = 0; k < 16; ++k) {
            float w0 = sW1[k * 64 + lane];
            float w1 = sW1[k * 64 + lane + 32];
#pragma unroll
            for (int i = 0; i < NPW; ++i) {
                float fk = __shfl_sync(FULL, f[i], k);
                u0[i] = fmaf(fk, w0, u0[i]);
                u1[i] = fmaf(fk, w1, u1[i]);
            }
        }
#pragma unroll
        for (int i = 0; i < NPW; ++i) {
            u0[i] = lrelu(u0[i], 0.1f);
            u1[i] = lrelu(u1[i], 0.1f);
        }

        unsigned long long a0[NPW], a1[NPW];
#pragma unroll
        for (int i = 0; i < NPW; ++i) {
            a0[i] = pk2(sbA[l4], sbA[l4 + 1]);
            a1[i] = pk2(sbA[l4 + 2], sbA[l4 + 3]);
        }
#pragma unroll 4
        for (int k = 0; k < 64; ++k) {
            ulonglong2 w = *(const ulonglong2*)&sW2h[k * 128 + l4];
#pragma unroll
            for (int i = 0; i < NPW; ++i) {
                float uk = (k < 32) ? __shfl_sync(FULL, u0[i], k)
                                    : __shfl_sync(FULL, u1[i], k - 32);
                unsigned long long uu = pk2(uk, uk);
                a0[i] = fma2(uu, w.x, a0[i]);
                a1[i] = fma2(uu, w.y, a1[i]);
            }
        }
        float4 at = *(const float4*)&sattn[l4];
        float av4[NPW];
#pragma unroll
        for (int i = 0; i < NPW; ++i) {
            int v = v0 + i;
            if (!full && v >= NN) { av4[i] = 0.f; continue; }
            float2 x01 = upk2(a0[i]), x23 = upk2(a1[i]);
            __half2 h0 = __floats2half2_rn(x01.x, x01.y);
            __half2 h1 = __floats2half2_rn(x23.x, x23.y);
            uint2 hp;
            hp.x = *(unsigned*)&h0;
            hp.y = *(unsigned*)&h1;
            *(uint2*)&g_Ah[(size_t)v * 64 + 2 * lane] = hp;
            av4[i] = x01.x * at.x + x01.y * at.y + x23.x * at.z + x23.y * at.w;
        }

        unsigned long long c0[NPW], c1[NPW];
#pragma unroll
        for (int i = 0; i < NPW; ++i) {
            c0[i] = pk2(sbnm[l4], sbnm[l4 + 1]);
            c1[i] = pk2(sbnm[l4 + 2], sbnm[l4 + 3]);
        }
#pragma unroll
        for (int k = 0; k < 16; ++k) {
            ulonglong2 w = *(const ulonglong2*)&sWf[k * 128 + l4];
#pragma unroll
            for (int i = 0; i < NPW; ++i) {
                float fk = __shfl_sync(FULL, f[i], k);
                unsigned long long ff = pk2(fk, fk);
                c0[i] = fma2(ff, w.x, c0[i]);
                c1[i] = fma2(ff, w.y, c1[i]);
            }
        }
#pragma unroll
        for (int i = 0; i < NPW; ++i) {
            int v = v0 + i;
            if (!full && v >= NN) continue;
            float2 b01 = upk2(c0[i]), b23 = upk2(c1[i]);
            float4 b = make_float4(b01.x, b01.y, b23.x, b23.y);
            *(float4*)&g_B[(size_t)v * 128 + l4] = b;
            float ps = av4[i];
            float pd = b.x * at.x + b.y * at.y + b.z * at.z + b.w * at.w;
#pragma unroll
            for (int s = 16; s > 0; s >>= 1) {
                ps += __shfl_xor_sync(FULL, ps, s);
                pd += __shfl_xor_sync(FULL, pd, s);
            }
            if (lane == 0) { g_as[v] = ps; g_ad[v] = pd; }
        }
    }
}

// ---------------- CSR build -------------------------------------------------
__global__ void k2_zero() {
    int i = blockIdx.x * blockDim.x + threadIdx.x;
    if (i < NN) g_deg[i] = 0;
}
__global__ void k2_hist(const int* __restrict__ dst) {
    int i = blockIdx.x * blockDim.x + threadIdx.x;
    if (i < EE) atomicAdd(&g_deg[dst[i]], 1);
}

// 3-phase parallel exclusive scan of g_deg -> g_off / g_cur
__global__ __launch_bounds__(512) void kS1_sum() {
    __shared__ int s[512];
    int tid = threadIdx.x;
    int i = blockIdx.x * 512 + tid;
    int v = (i < NN) ? g_deg[i] : 0;
    s[tid] = v;
    __syncthreads();
#pragma unroll
    for (int o = 256; o > 0; o >>= 1) {
        if (tid < o) s[tid] += s[tid + o];
        __syncthreads();
    }
    if (tid == 0) g_bsum[blockIdx.x] = s[0];
}
__global__ __launch_bounds__(256) void kS2_scanb() {
    __shared__ int s[256];
    int tid = threadIdx.x;
    int v = (tid < NB) ? g_bsum[tid] : 0;
    s[tid] = v;
    __syncthreads();
    for (int o = 1; o < 256; o <<= 1) {
        int t = (tid >= o) ? s[tid - o] : 0;
        __syncthreads();
        s[tid] += t;
        __syncthreads();
    }
    if (tid < NB) g_bbase[tid] = s[tid] - v;   // exclusive
    if (tid == NB - 1) g_off[NN] = s[tid];     // total
}
__global__ __launch_bounds__(512) void kS3_local() {
    __shared__ int s[512];
    int tid = threadIdx.x;
    int i = blockIdx.x * 512 + tid;
    int v = (i < NN) ? g_deg[i] : 0;
    s[tid] = v;
    __syncthreads();
    for (int o = 1; o < 512; o <<= 1) {
        int t = (tid >= o) ? s[tid - o] : 0;
        __syncthreads();
        s[tid] += t;
        __syncthreads();
    }
    if (i < NN) {
        int excl = s[tid] - v + g_bbase[blockIdx.x];
        g_off[i] = excl;
        g_cur[i] = excl;
    }
}

// scatter + edge logit + exp folded in (no max-shift needed: |logit| <~ 10,
// exp is fp32-safe unshifted; softmax alpha is mathematically identical)
__global__ void k2_scatter(const int* __restrict__ src,
                           const int* __restrict__ dst,
                           const float* __restrict__ bit) {
    int i = blockIdx.x * blockDim.x + threadIdx.x;
    if (i < EE) {
        int s = src[i], d = dst[i];
        float bv = bit[i];
        float lg = g_as[s] + g_ad[d] + g_c * bv;
        lg = fmaxf(lg, 0.2f * lg);
        float ee = __expf(lg);
        int pos = atomicAdd(&g_cur[d], 1);
        g_srcv[pos] = s;
        g_lb[pos] = make_float2(ee, ee * bv);
    }
}

// ---------------- k3: softmax-agg + out MLP fused (warp per node) ----------
// W_out1 read straight from L1/L2 (16 KB, hot) -> tiny smem -> high occupancy
__global__ __launch_bounds__(256, 4) void k3_fused(
    const float* __restrict__ W_nm,
    const float* __restrict__ W1, const float* __restrict__ b1,
    const float* __restrict__ W2, const float* __restrict__ b2,
    float* __restrict__ out) {
    __shared__ __align__(16) float sb1[128];
    __shared__ __align__(16) float sW2[128];
    __shared__ __align__(16) float swb[128];
    int tid = threadIdx.x;
    if (tid < 128) { sb1[tid] = b1[tid]; sW2[tid] = W2[tid]; swb[tid] = W_nm[128 * 128 + tid]; }
    __syncthreads();
    float b2v = b2[0];

    int warp = tid >> 5, lane = tid & 31;
    int l4 = 4 * lane;
    const unsigned FULL = 0xffffffffu;

    for (int base = blockIdx.x * 8; base < NN; base += gridDim.x * 8) {
        int v = base + warp;
        if (v >= NN) continue;

        int s0 = g_off[v], s1 = g_off[v + 1];
        float4 hn = make_float4(0.f, 0.f, 0.f, 0.f);
        if (s0 < s1) {
            unsigned long long acc0 = 0ull, acc1 = 0ull;
            float se = 0.f, st = 0.f;
            for (int cb = s0; cb < s1; cb += 32) {
                int n = min(32, s1 - cb);
                int svl = 0; float eel = 0.f;
                if (lane < n) {
                    svl = __ldg(&g_srcv[cb + lane]);
                    float2 lb = __ldg(&g_lb[cb + lane]);
                    eel = lb.x;
                    se += lb.x;          // lane-parallel scalar sums
                    st += lb.y;
                }
#pragma unroll 4
                for (int j = 0; j < n; ++j) {
                    int   sv = __shfl_sync(FULL, svl, j);
                    float ee = __shfl_sync(FULL, eel, j);
                    uint2 raw = __ldg((const uint2*)&g_Ah[(size_t)sv * 64 + 2 * lane]);
                    float2 f0 = __half22float2(*(__half2*)&raw.x);
                    float2 f1 = __half22float2(*(__half2*)&raw.y);
                    unsigned long long ev = pk2(ee, ee);
                    acc0 = fma2(ev, pk2(f0.x, f0.y), acc0);
                    acc1 = fma2(ev, pk2(f1.x, f1.y), acc1);
                }
            }
#pragma unroll
            for (int o = 16; o > 0; o >>= 1) {
                se += __shfl_xor_sync(FULL, se, o);
                st += __shfl_xor_sync(FULL, st, o);
            }
            float inv = 1.f / se;
            float tb = st * inv;
            float2 a01 = upk2(acc0), a23 = upk2(acc1);
            float4 B4 = __ldg((const float4*)&g_B[(size_t)v * 128 + l4]);
            float4 wb = *(const float4*)&swb[l4];
            hn.x = fmaxf(fmaf(a01.x, inv, B4.x) + wb.x * tb, 0.f);
            hn.y = fmaxf(fmaf(a01.y, inv, B4.y) + wb.y * tb, 0.f);
            hn.z = fmaxf(fmaf(a23.x, inv, B4.z) + wb.z * tb, 0.f);
            hn.w = fmaxf(fmaf(a23.y, inv, B4.w) + wb.w * tb, 0.f);
        }

        // out MLP: acc = lrelu(hn @ W_out1 + b_out1); out = acc . W_out2 + b2
        unsigned long long o0 = pk2(sb1[l4], sb1[l4 + 1]);
        unsigned long long o1 = pk2(sb1[l4 + 2], sb1[l4 + 3]);
#pragma unroll 8
        for (int k = 0; k < 128; ++k) {
            float s;
            switch (k & 3) {
                case 0: s = hn.x; break;
                case 1: s = hn.y; break;
                case 2: s = hn.z; break;
                default: s = hn.w; break;
            }
            float val = __shfl_sync(FULL, s, k >> 2);
            if (val != 0.f) {          // hn is post-ReLU: ~half zeros, warp-uniform skip
                ulonglong2 w = __ldg((const ulonglong2*)&W1[k * 128 + l4]);
                unsigned long long vv = pk2(val, val);
                o0 = fma2(vv, w.x, o0);
                o1 = fma2(vv, w.y, o1);
            }
        }
        float2 q01 = upk2(o0), q23 = upk2(o1);
        float4 acc = make_float4(lrelu(q01.x, 0.1f), lrelu(q01.y, 0.1f),
                                 lrelu(q23.x, 0.1f), lrelu(q23.y, 0.1f));
        float4 w2 = *(const float4*)&sW2[l4];
        float p = acc.x * w2.x + acc.y * w2.y + acc.z * w2.z + acc.w * w2.w;
#pragma unroll
        for (int o = 16; o > 0; o >>= 1) p += __shfl_xor_sync(FULL, p, o);
        if (lane == 0) out[v] = p + b2v;
    }
}

// ---------------- launch -----------------------------------------------------
extern "C" void kernel_launch(void* const* d_in, const int* in_sizes, int n_in,
                              void* d_out, int out_size) {
    const float* feat    = (const float*)d_in[0];
    const float* bit     = (const float*)d_in[1];
    const int*   src     = (const int*)d_in[2];
    const int*   dst     = (const int*)d_in[3];
    const float* W_self1 = (const float*)d_in[4];
    const float* b_self1 = (const float*)d_in[5];
    const float* W_self2 = (const float*)d_in[6];
    const float* b_self2 = (const float*)d_in[7];
    const float* W_nm    = (const float*)d_in[8];
    const float* b_nm    = (const float*)d_in[9];
    const float* attn    = (const float*)d_in[10];
    const float* W_out1  = (const float*)d_in[11];
    const float* b_out1  = (const float*)d_in[12];
    const float* W_out2  = (const float*)d_in[13];
    const float* b_out2  = (const float*)d_in[14];
    float* out = (float*)d_out;

    k2_zero<<<(NN + 255) / 256, 256>>>();
    k0_prep<<<65, 128>>>(W_self2, b_self2, W_nm, attn);
    k2_hist<<<(EE + 255) / 256, 256>>>(dst);
    k1_node<<<592, 256>>>(feat, W_self1, b_self1, W_nm, b_nm, attn);
    kS1_sum<<<NB, 512>>>();
    kS2_scanb<<<1, 256>>>();
    kS3_local<<<NB, 512>>>();
    k2_scatter<<<(EE + 255) / 256, 256>>>(src, dst, bit);
    k3_fused<<<444, 256>>>(W_nm, W_out1, b_out1, W_out2, b_out2, out);
}

// round 10
// speedup vs baseline: 1.0982x; 1.0720x over previous
#include <cuda_runtime.h>
#include <cuda_fp16.h>
#include <math.h>

#define NN 100000
#define EE 1600000
#define FF 16
#define HH 128
#define NB 196            // scan blocks: ceil(NN/512)

// ---------------- scratch (device globals; no allocation allowed) ----------
__device__ __align__(16) __half2 g_Ah[(size_t)NN * 64];  // h @ W_h (fp16, 256B/row)
__device__ __align__(16) float g_B[(size_t)NN * HH];     // feat @ W_f + b_nm
__device__ float g_as[NN];
__device__ float g_ad[NN];
__device__ int   g_deg[NN];
__device__ int   g_off[NN + 1];
__device__ int   g_cur[NN];
__device__ int   g_bsum[NB];
__device__ int   g_bbase[NB];
__device__ int   g_srcv[EE];                    // CSR-ordered src node
__device__ __align__(8) float2 g_lb[EE];        // CSR-ordered (ee, ee*bit)
__device__ __align__(16) float g_W2h[64 * HH];
__device__ __align__(16) float g_bA[HH];
__device__ float g_c;

__device__ __forceinline__ float lrelu(float x, float s) { return fmaxf(x, s * x); }

// packed fp32x2 helpers (Blackwell FFMA2: 2x fp32 FMA issue rate)
__device__ __forceinline__ unsigned long long pk2(float x, float y) {
    unsigned long long r; asm("mov.b64 %0,{%1,%2};" : "=l"(r) : "f"(x), "f"(y)); return r;
}
__device__ __forceinline__ float2 upk2(unsigned long long v) {
    float2 r; asm("mov.b64 {%0,%1},%2;" : "=f"(r.x), "=f"(r.y) : "l"(v)); return r;
}
__device__ __forceinline__ unsigned long long fma2(unsigned long long a,
                                                   unsigned long long b,
                                                   unsigned long long c) {
    unsigned long long d;
    asm("fma.rn.f32x2 %0,%1,%2,%3;" : "=l"(d) : "l"(a), "l"(b), "l"(c));
    return d;
}

// ---------------- k0: fold W_self2 into W_h; bias; scalar c ----------------
__global__ void k0_prep(const float* __restrict__ W_self2,
                        const float* __restrict__ b_self2,
                        const float* __restrict__ W_nm,
                        const float* __restrict__ attn) {
    int j = threadIdx.x;          // 0..127
    int i = blockIdx.x;           // 0..64
    if (i < 64) {
        float acc = 0.f;
        for (int k = 0; k < 128; ++k)
            acc = fmaf(W_self2[i * 128 + k], W_nm[k * 128 + j], acc);
        g_W2h[i * 128 + j] = acc;
    } else {
        float acc = 0.f;
        for (int k = 0; k < 128; ++k)
            acc = fmaf(b_self2[k], W_nm[k * 128 + j], acc);
        g_bA[j] = acc;
        __shared__ float red[128];
        red[j] = W_nm[128 * 128 + j] * attn[j];   // row 128 of W_nm = w_b
        __syncthreads();
        for (int s = 64; s > 0; s >>= 1) {
            if (j < s) red[j] += red[j + s];
            __syncthreads();
        }
        if (j == 0) g_c = red[0];
    }
}

// ---------------- k1: per-node A(fp16), B, a_s, a_d -------------------------
// 4 nodes per warp per iteration (R7 optimum: NPW=8 crushed occupancy)
#define NPW 4
__global__ __launch_bounds__(256) void k1_node(
    const float* __restrict__ feat,
    const float* __restrict__ W1, const float* __restrict__ b1,
    const float* __restrict__ W_nm, const float* __restrict__ b_nm,
    const float* __restrict__ attn) {
    __shared__ __align__(16) float sW1[16 * 64];
    __shared__ __align__(16) float sW2h[64 * 128];
    __shared__ __align__(16) float sWf[16 * 128];
    __shared__ __align__(16) float sb1[64];
    __shared__ __align__(16) float sbnm[128];
    __shared__ __align__(16) float sbA[128];
    __shared__ __align__(16) float sattn[128];
    int tid = threadIdx.x;
    for (int i = tid; i < 16 * 64; i += 256) sW1[i] = W1[i];
    for (int i = tid; i < 64 * 128; i += 256) sW2h[i] = g_W2h[i];
    for (int i = tid; i < 16 * 128; i += 256) sWf[i] = W_nm[129 * 128 + i];
    if (tid < 64) sb1[tid] = b1[tid];
    if (tid < 128) { sbnm[tid] = b_nm[tid]; sbA[tid] = g_bA[tid]; sattn[tid] = attn[tid]; }
    __syncthreads();

    int warp = tid >> 5, lane = tid & 31;
    const unsigned FULL = 0xffffffffu;
    int l4 = 4 * lane;
    const int STRIDE = 8 * NPW;   // nodes per block per iteration

    for (int base = blockIdx.x * STRIDE; base < NN; base += gridDim.x * STRIDE) {
        int v0 = base + warp * NPW;
        if (v0 >= NN) continue;
        bool full = (v0 + NPW <= NN);

        float f[NPW];
#pragma unroll
        for (int i = 0; i < NPW; ++i) {
            int v = v0 + i;
            f[i] = (lane < 16 && (full || v < NN)) ? feat[(size_t)v * 16 + lane] : 0.f;
        }

        float u0[NPW], u1[NPW];
#pragma unroll
        for (int i = 0; i < NPW; ++i) { u0[i] = sb1[lane]; u1[i] = sb1[lane + 32]; }
#pragma unroll
        for (int k = 0; k < 16; ++k) {
            float w0 = sW1[k * 64 + lane];
            float w1 = sW1[k * 64 + lane + 32];
#pragma unroll
            for (int i = 0; i < NPW; ++i) {
                float fk = __shfl_sync(FULL, f[i], k);
                u0[i] = fmaf(fk, w0, u0[i]);
                u1[i] = fmaf(fk, w1, u1[i]);
            }
        }
#pragma unroll
        for (int i = 0; i < NPW; ++i) {
            u0[i] = lrelu(u0[i], 0.1f);
            u1[i] = lrelu(u1[i], 0.1f);
        }

        unsigned long long a0[NPW], a1[NPW];
#pragma unroll
        for (int i = 0; i < NPW; ++i) {
            a0[i] = pk2(sbA[l4], sbA[l4 + 1]);
            a1[i] = pk2(sbA[l4 + 2], sbA[l4 + 3]);
        }
#pragma unroll 8
        for (int k = 0; k < 64; ++k) {
            ulonglong2 w = *(const ulonglong2*)&sW2h[k * 128 + l4];
#pragma unroll
            for (int i = 0; i < NPW; ++i) {
                float uk = (k < 32) ? __shfl_sync(FULL, u0[i], k)
                                    : __shfl_sync(FULL, u1[i], k - 32);
                unsigned long long uu = pk2(uk, uk);
                a0[i] = fma2(uu, w.x, a0[i]);
                a1[i] = fma2(uu, w.y, a1[i]);
            }
        }
        float4 at = *(const float4*)&sattn[l4];
        float av4[NPW];
#pragma unroll
        for (int i = 0; i < NPW; ++i) {
            int v = v0 + i;
            if (!full && v >= NN) { av4[i] = 0.f; continue; }
            float2 x01 = upk2(a0[i]), x23 = upk2(a1[i]);
            __half2 h0 = __floats2half2_rn(x01.x, x01.y);
            __half2 h1 = __floats2half2_rn(x23.x, x23.y);
            uint2 hp;
            hp.x = *(unsigned*)&h0;
            hp.y = *(unsigned*)&h1;
            *(uint2*)&g_Ah[(size_t)v * 64 + 2 * lane] = hp;
            av4[i] = x01.x * at.x + x01.y * at.y + x23.x * at.z + x23.y * at.w;
        }

        unsigned long long c0[NPW], c1[NPW];
#pragma unroll
        for (int i = 0; i < NPW; ++i) {
            c0[i] = pk2(sbnm[l4], sbnm[l4 + 1]);
            c1[i] = pk2(sbnm[l4 + 2], sbnm[l4 + 3]);
        }
#pragma unroll
        for (int k = 0; k < 16; ++k) {
            ulonglong2 w = *(const ulonglong2*)&sWf[k * 128 + l4];
#pragma unroll
            for (int i = 0; i < NPW; ++i) {
                float fk = __shfl_sync(FULL, f[i], k);
                unsigned long long ff = pk2(fk, fk);
                c0[i] = fma2(ff, w.x, c0[i]);
                c1[i] = fma2(ff, w.y, c1[i]);
            }
        }
#pragma unroll
        for (int i = 0; i < NPW; ++i) {
            int v = v0 + i;
            if (!full && v >= NN) continue;
            float2 b01 = upk2(c0[i]), b23 = upk2(c1[i]);
            float4 b = make_float4(b01.x, b01.y, b23.x, b23.y);
            *(float4*)&g_B[(size_t)v * 128 + l4] = b;
            float ps = av4[i];
            float pd = b.x * at.x + b.y * at.y + b.z * at.z + b.w * at.w;
#pragma unroll
            for (int s = 16; s > 0; s >>= 1) {
                ps += __shfl_xor_sync(FULL, ps, s);
                pd += __shfl_xor_sync(FULL, pd, s);
            }
            if (lane == 0) { g_as[v] = ps; g_ad[v] = pd; }
        }
    }
}

// ---------------- CSR build -------------------------------------------------
__global__ void k2_zero() {
    int i = blockIdx.x * blockDim.x + threadIdx.x;
    if (i < NN) g_deg[i] = 0;
}
__global__ void k2_hist(const int* __restrict__ dst) {
    int i = blockIdx.x * blockDim.x + threadIdx.x;
    if (i < EE) atomicAdd(&g_deg[dst[i]], 1);
}

// 3-phase parallel exclusive scan of g_deg -> g_off / g_cur
__global__ __launch_bounds__(512) void kS1_sum() {
    __shared__ int s[512];
    int tid = threadIdx.x;
    int i = blockIdx.x * 512 + tid;
    int v = (i < NN) ? g_deg[i] : 0;
    s[tid] = v;
    __syncthreads();
#pragma unroll
    for (int o = 256; o > 0; o >>= 1) {
        if (tid < o) s[tid] += s[tid + o];
        __syncthreads();
    }
    if (tid == 0) g_bsum[blockIdx.x] = s[0];
}
__global__ __launch_bounds__(256) void kS2_scanb() {
    __shared__ int s[256];
    int tid = threadIdx.x;
    int v = (tid < NB) ? g_bsum[tid] : 0;
    s[tid] = v;
    __syncthreads();
    for (int o = 1; o < 256; o <<= 1) {
        int t = (tid >= o) ? s[tid - o] : 0;
        __syncthreads();
        s[tid] += t;
        __syncthreads();
    }
    if (tid < NB) g_bbase[tid] = s[tid] - v;   // exclusive
    if (tid == NB - 1) g_off[NN] = s[tid];     // total
}
__global__ __launch_bounds__(512) void kS3_local() {
    __shared__ int s[512];
    int tid = threadIdx.x;
    int i = blockIdx.x * 512 + tid;
    int v = (i < NN) ? g_deg[i] : 0;
    s[tid] = v;
    __syncthreads();
    for (int o = 1; o < 512; o <<= 1) {
        int t = (tid >= o) ? s[tid - o] : 0;
        __syncthreads();
        s[tid] += t;
        __syncthreads();
    }
    if (i < NN) {
        int excl = s[tid] - v + g_bbase[blockIdx.x];
        g_off[i] = excl;
        g_cur[i] = excl;
    }
}

// scatter + edge logit + exp folded in (no max-shift needed: |logit| <~ 10,
// exp is fp32-safe unshifted; softmax alpha is mathematically identical)
__global__ void k2_scatter(const int* __restrict__ src,
                           const int* __restrict__ dst,
                           const float* __restrict__ bit) {
    int i = blockIdx.x * blockDim.x + threadIdx.x;
    if (i < EE) {
        int s = src[i], d = dst[i];
        float bv = bit[i];
        float lg = g_as[s] + g_ad[d] + g_c * bv;
        lg = fmaxf(lg, 0.2f * lg);
        float ee = __expf(lg);
        int pos = atomicAdd(&g_cur[d], 1);
        g_srcv[pos] = s;
        g_lb[pos] = make_float2(ee, ee * bv);
    }
}

// ---------------- k3: softmax-agg + out MLP fused (warp per node) ----------
// W_out1 read straight from L1/L2 (16 KB, hot) -> tiny smem -> high occupancy
__global__ __launch_bounds__(256, 4) void k3_fused(
    const float* __restrict__ W_nm,
    const float* __restrict__ W1, const float* __restrict__ b1,
    const float* __restrict__ W2, const float* __restrict__ b2,
    float* __restrict__ out) {
    __shared__ __align__(16) float sb1[128];
    __shared__ __align__(16) float sW2[128];
    __shared__ __align__(16) float swb[128];
    int tid = threadIdx.x;
    if (tid < 128) { sb1[tid] = b1[tid]; sW2[tid] = W2[tid]; swb[tid] = W_nm[128 * 128 + tid]; }
    __syncthreads();
    float b2v = b2[0];

    int warp = tid >> 5, lane = tid & 31;
    int l4 = 4 * lane;
    const unsigned FULL = 0xffffffffu;

    for (int base = blockIdx.x * 8; base < NN; base += gridDim.x * 8) {
        int v = base + warp;
        if (v >= NN) continue;

        int s0 = g_off[v], s1 = g_off[v + 1];
        float4 hn = make_float4(0.f, 0.f, 0.f, 0.f);
        if (s0 < s1) {
            unsigned long long acc0 = 0ull, acc1 = 0ull;
            float se = 0.f, st = 0.f;
            for (int cb = s0; cb < s1; cb += 32) {
                int n = min(32, s1 - cb);
                int svl = 0; float eel = 0.f;
                if (lane < n) {
                    svl = __ldg(&g_srcv[cb + lane]);
                    float2 lb = __ldg(&g_lb[cb + lane]);
                    eel = lb.x;
                    se += lb.x;          // lane-parallel scalar sums
                    st += lb.y;
                }
#pragma unroll 4
                for (int j = 0; j < n; ++j) {
                    int   sv = __shfl_sync(FULL, svl, j);
                    float ee = __shfl_sync(FULL, eel, j);
                    uint2 raw = __ldg((const uint2*)&g_Ah[(size_t)sv * 64 + 2 * lane]);
                    float2 f0 = __half22float2(*(__half2*)&raw.x);
                    float2 f1 = __half22float2(*(__half2*)&raw.y);
                    unsigned long long ev = pk2(ee, ee);
                    acc0 = fma2(ev, pk2(f0.x, f0.y), acc0);
                    acc1 = fma2(ev, pk2(f1.x, f1.y), acc1);
                }
            }
#pragma unroll
            for (int o = 16; o > 0; o >>= 1) {
                se += __shfl_xor_sync(FULL, se, o);
                st += __shfl_xor_sync(FULL, st, o);
            }
            float inv = 1.f / se;
            float tb = st * inv;
            float2 a01 = upk2(acc0), a23 = upk2(acc1);
            float4 B4 = __ldg((const float4*)&g_B[(size_t)v * 128 + l4]);
            float4 wb = *(const float4*)&swb[l4];
            hn.x = fmaxf(fmaf(a01.x, inv, B4.x) + wb.x * tb, 0.f);
            hn.y = fmaxf(fmaf(a01.y, inv, B4.y) + wb.y * tb, 0.f);
            hn.z = fmaxf(fmaf(a23.x, inv, B4.z) + wb.z * tb, 0.f);
            hn.w = fmaxf(fmaf(a23.y, inv, B4.w) + wb.w * tb, 0.f);
        }

        // out MLP: acc = lrelu(hn @ W_out1 + b_out1); out = acc . W_out2 + b2
        unsigned long long o0 = pk2(sb1[l4], sb1[l4 + 1]);
        unsigned long long o1 = pk2(sb1[l4 + 2], sb1[l4 + 3]);
#pragma unroll 8
        for (int k = 0; k < 128; ++k) {
            float s;
            switch (k & 3) {
                case 0: s = hn.x; break;
                case 1: s = hn.y; break;
                case 2: s = hn.z; break;
                default: s = hn.w; break;
            }
            float val = __shfl_sync(FULL, s, k >> 2);
            if (val != 0.f) {          // hn is post-ReLU: ~half zeros, warp-uniform skip
                ulonglong2 w = __ldg((const ulonglong2*)&W1[k * 128 + l4]);
                unsigned long long vv = pk2(val, val);
                o0 = fma2(vv, w.x, o0);
                o1 = fma2(vv, w.y, o1);
            }
        }
        float2 q01 = upk2(o0), q23 = upk2(o1);
        float4 acc = make_float4(lrelu(q01.x, 0.1f), lrelu(q01.y, 0.1f),
                                 lrelu(q23.x, 0.1f), lrelu(q23.y, 0.1f));
        float4 w2 = *(const float4*)&sW2[l4];
        float p = acc.x * w2.x + acc.y * w2.y + acc.z * w2.z + acc.w * w2.w;
#pragma unroll
        for (int o = 16; o > 0; o >>= 1) p += __shfl_xor_sync(FULL, p, o);
        if (lane == 0) out[v] = p + b2v;
    }
}

// ---------------- launch -----------------------------------------------------
extern "C" void kernel_launch(void* const* d_in, const int* in_sizes, int n_in,
                              void* d_out, int out_size) {
    const float* feat    = (const float*)d_in[0];
    const float* bit     = (const float*)d_in[1];
    const int*   src     = (const int*)d_in[2];
    const int*   dst     = (const int*)d_in[3];
    const float* W_self1 = (const float*)d_in[4];
    const float* b_self1 = (const float*)d_in[5];
    const float* W_self2 = (const float*)d_in[6];
    const float* b_self2 = (const float*)d_in[7];
    const float* W_nm    = (const float*)d_in[8];
    const float* b_nm    = (const float*)d_in[9];
    const float* attn    = (const float*)d_in[10];
    const float* W_out1  = (const float*)d_in[11];
    const float* b_out1  = (const float*)d_in[12];
    const float* W_out2  = (const float*)d_in[13];
    const float* b_out2  = (const float*)d_in[14];
    float* out = (float*)d_out;

    k2_zero<<<(NN + 255) / 256, 256>>>();
    k0_prep<<<65, 128>>>(W_self2, b_self2, W_nm, attn);
    k2_hist<<<(EE + 255) / 256, 256>>>(dst);
    k1_node<<<592, 256>>>(feat, W_self1, b_self1, W_nm, b_nm, attn);
    kS1_sum<<<NB, 512>>>();
    kS2_scanb<<<1, 256>>>();
    kS3_local<<<NB, 512>>>();
    k2_scatter<<<(EE + 255) / 256, 256>>>(src, dst, bit);
    k3_fused<<<592, 256>>>(W_nm, W_out1, b_out1, W_out2, b_out2, out);
}